// round 7
// baseline (speedup 1.0000x reference)
#include <cuda_runtime.h>
#include <cuda_bf16.h>
#include <cstdint>

// ROI Align (torchvision semantics), OUT 7x7, adaptive grid <= 4x4.
// features: [B=4, C=256, H=200, W=272] fp32 NCHW
// rois:     [N=512, 5] (b, x1, y1, x2, y2) fp32
// out:      [N, C, 7, 7] fp32
//
// R7: issue/ALU reduction on top of the TMA bulk staging skeleton:
//  - balanced (bin, channel-pair) thread mapping: 196 threads, 1 bin each,
//    2 channels at constant +CPITCH (folded into LDS immediates)
//  - gw-specialized unrolled tap loops (uniform switch per block)
//  - dynamic staging extent (only rows/cols the ROI can touch), expect_tx
//    matched; meta offsets clamped to staged extent (no NaN garbage reads)

#define OUT_H 7
#define OUT_W 7
#define NBINS 49
#define MAXG  4
#define C_TILE 8
#define REG   30               // max staged rows
#define WCOLS 36               // staged row pitch in floats (144B)
#define CPITCH 1084            // floats per channel: 30*36 +4 pad; %32==28,
                               // *4 %16==0 (bulk dst align)

#define FEAT_C 256
#define FEAT_H 200
#define FEAT_W 272
#define FEAT_HW (FEAT_H * FEAT_W)

__device__ __forceinline__ uint32_t smem_u32(const void* p) {
    uint32_t a;
    asm("{ .reg .u64 t; cvta.to.shared.u64 t, %1; cvt.u32.u64 %0, t; }"
        : "=r"(a) : "l"(p));
    return a;
}

struct __align__(16) SmemLayout {
    float    region[C_TILE * CPITCH];   // [c][row][36]
    float    s_out[C_TILE * NBINS];
    float4   ymeta[OUT_H * MAXG];       // wy0, wy1, rl*36, rh*36
    float4   xmeta[OUT_H * MAXG];       // wx0, wx1, cl, ch
    unsigned long long mbar;
};

// accumulate one bin for 2 channels; channel 1 at regc0 + CPITCH (const)
template<int GW>
__device__ __forceinline__ void bin_acc(const float* __restrict__ regc0,
                                        const float4* __restrict__ ym,
                                        const float4* __restrict__ xm,
                                        int gh, float& a0, float& a1)
{
    for (int iy = 0; iy < gh; ++iy) {
        const float4 my = ym[iy];
        const int ol = __float_as_int(my.z);
        const int oh = __float_as_int(my.w);
        const float wy0 = my.x, wy1 = my.y;
        #pragma unroll
        for (int ix = 0; ix < GW; ++ix) {
            const float4 mx = xm[ix];
            const int cl = __float_as_int(mx.z);
            const int ch = __float_as_int(mx.w);
            const int i00 = ol + cl, i01 = ol + ch, i10 = oh + cl, i11 = oh + ch;
            // channel 0
            {
                const float t0 = mx.x * regc0[i00] + mx.y * regc0[i01];
                const float t1 = mx.x * regc0[i10] + mx.y * regc0[i11];
                a0 += wy0 * t0 + wy1 * t1;
            }
            // channel 1 (constant offset -> LDS immediate)
            {
                const float t0 = mx.x * regc0[CPITCH + i00] + mx.y * regc0[CPITCH + i01];
                const float t1 = mx.x * regc0[CPITCH + i10] + mx.y * regc0[CPITCH + i11];
                a1 += wy0 * t0 + wy1 * t1;
            }
        }
    }
}

__global__ __launch_bounds__(256)
void roi_align_kernel(const float* __restrict__ feat,
                      const float* __restrict__ rois,
                      float* __restrict__ out)
{
    __shared__ SmemLayout sm;

    const int H = FEAT_H, W = FEAT_W;
    const int blk = blockIdx.x;
    const int n   = blk & 511;        // roi index
    const int ct  = blk >> 9;         // channel tile (slice-major for L2 reuse)

    const float* r = rois + n * 5;
    const int   bidx  = (int)r[0];
    const float x1    = r[1];
    const float y1    = r[2];
    const float roi_w = fmaxf(r[3] - x1, 1.0f);
    const float roi_h = fmaxf(r[4] - y1, 1.0f);
    const float bin_h = roi_h * (1.0f / OUT_H);
    const float bin_w = roi_w * (1.0f / OUT_W);
    int gh = (int)ceilf(roi_h * (1.0f / OUT_H)); gh = min(max(gh, 1), MAXG);
    int gw = (int)ceilf(roi_w * (1.0f / OUT_W)); gw = min(max(gw, 1), MAXG);

    const int ry0 = min(max((int)floorf(y1), 0), H - 1);
    const int rx0 = min(max((int)floorf(x1), 0), W - 1);
    const int ax0 = min(rx0 & ~3, W - WCOLS);   // aligned window, in-bounds

    // dynamic staged extent (max row/col any tap can reference, see analysis)
    const int ymax = min((int)floorf(y1 + roi_h) + 1, H - 1);
    const int rows_used = min(REG, ymax - ry0 + 1);            // >= 1
    const int xmax = min((int)floorf(x1 + roi_w) + 1, W - 1);
    const int cols_f = min(WCOLS, ((xmax - ax0 + 1 + 3) & ~3)); // mult of 4
    const int cols_bytes = cols_f * 4;                          // mult of 16

    const int tid = threadIdx.x;
    const uint32_t mbar = smem_u32(&sm.mbar);

    // ---- init mbarrier + expect exact staging byte count ----
    if (tid == 0) {
        asm volatile("mbarrier.init.shared.b64 [%0], 1;" :: "r"(mbar) : "memory");
        asm volatile("mbarrier.arrive.expect_tx.shared.b64 _, [%0], %1;"
                     :: "r"(mbar), "r"(C_TILE * rows_used * cols_bytes) : "memory");
    }
    __syncthreads();

    // ---- phase 1: enqueue bulk row copies (only the rows we need) ----
    if (tid < C_TILE * REG) {
        const int c   = tid / REG;
        const int row = tid - c * REG;
        if (row < rows_used) {
            const float* src = feat
                + ((size_t)bidx * FEAT_C + (size_t)(ct * C_TILE + c)) * (size_t)FEAT_HW
                + (size_t)(ry0 + row) * W + ax0;
            const uint32_t dst = smem_u32(sm.region)
                               + (uint32_t)((c * CPITCH + row * WCOLS) * 4);
            asm volatile(
                "cp.async.bulk.shared::cluster.global.mbarrier::complete_tx::bytes "
                "[%0], [%1], %2, [%3];"
                :: "r"(dst), "l"(src), "r"(cols_bytes), "r"(mbar) : "memory");
        }
    }

    // ---- phase 0 (overlapped with DMA): weights + premult clamped offsets ----
    if (tid < 2 * OUT_H * MAXG) {
        const bool isx = (tid >= OUT_H * MAXG);
        const int  t   = isx ? tid - OUT_H * MAXG : tid;
        const int  p   = t >> 2;          // output bin index along axis
        const int  gg  = t & 3;           // grid slot
        const float start = isx ? x1 : y1;
        const float binsz = isx ? bin_w : bin_h;
        const int   gcnt  = isx ? gw : gh;
        const int   size  = isx ? W : H;
        const float pos = start + (float)p * binsz + ((float)gg + 0.5f) * binsz / (float)gcnt;
        const bool valid = (pos >= -1.0f) && (pos <= (float)size);
        float pp = fmaxf(pos, 0.0f);
        int low = min((int)floorf(pp), size - 1);
        if (low >= size - 1) pp = (float)(size - 1);
        const float frac = pp - (float)low;
        const float m = valid ? 1.0f : 0.0f;
        const int hi = min(low + 1, size - 1);
        float4 mv;
        mv.x = (1.0f - frac) * m;
        mv.y = frac * m;
        if (isx) {
            mv.z = __int_as_float(min(max(low - ax0, 0), cols_f - 1));
            mv.w = __int_as_float(min(max(hi  - ax0, 0), cols_f - 1));
            sm.xmeta[t] = mv;
        } else {
            mv.z = __int_as_float(min(max(low - ry0, 0), rows_used - 1) * WCOLS);
            mv.w = __int_as_float(min(max(hi  - ry0, 0), rows_used - 1) * WCOLS);
            sm.ymeta[t] = mv;
        }
    }

    // ---- wait for DMA completion (parity 0: fresh barrier each launch) ----
    asm volatile(
        "{\n\t"
        ".reg .pred P;\n\t"
        "WAIT_%=:\n\t"
        "mbarrier.try_wait.parity.acquire.cta.shared::cta.b64 P, [%0], 0, 0x989680;\n\t"
        "@P bra DONE_%=;\n\t"
        "bra WAIT_%=;\n\t"
        "DONE_%=:\n\t"
        "}"
        :: "r"(mbar) : "memory");
    __syncthreads();   // also covers meta visibility

    // ---- phase 2: one (bin, channel-pair) per thread, 196 active ----
    if (tid < NBINS * (C_TILE / 2)) {
        const int cg  = tid / NBINS;          // channel pair 0..3
        const int bin = tid - cg * NBINS;     // 0..48
        const int ph  = bin / OUT_W;
        const int pw  = bin - ph * OUT_W;
        const float4* ym = sm.ymeta + ph * MAXG;
        const float4* xm = sm.xmeta + pw * MAXG;
        const float* regc0 = sm.region + (cg * 2) * CPITCH;
        float a0 = 0.0f, a1 = 0.0f;
        switch (gw) {
            case 1:  bin_acc<1>(regc0, ym, xm, gh, a0, a1); break;
            case 2:  bin_acc<2>(regc0, ym, xm, gh, a0, a1); break;
            case 3:  bin_acc<3>(regc0, ym, xm, gh, a0, a1); break;
            default: bin_acc<4>(regc0, ym, xm, gh, a0, a1); break;
        }
        const float inv = 1.0f / (float)(gh * gw);
        sm.s_out[(cg * 2) * NBINS + bin]     = a0 * inv;
        sm.s_out[(cg * 2 + 1) * NBINS + bin] = a1 * inv;
    }
    __syncthreads();

    // ---- phase 3: coalesced float4 output write ----
    {
        float4* ob4 = (float4*)(out + ((size_t)n * FEAT_C + (size_t)ct * C_TILE) * NBINS);
        const float4* so4 = (const float4*)sm.s_out;
        if (tid < (C_TILE * NBINS) / 4)      // 98 threads x 16B
            ob4[tid] = so4[tid];
    }
}

extern "C" void kernel_launch(void* const* d_in, const int* in_sizes, int n_in,
                              void* d_out, int out_size)
{
    const float* feat = (const float*)d_in[0];
    const float* rois = (const float*)d_in[1];
    float* out = (float*)d_out;
    const int N = in_sizes[1] / 5;

    roi_align_kernel<<<N * (FEAT_C / C_TILE), 256>>>(feat, rois, out);
}

// round 8
// speedup vs baseline: 1.2443x; 1.2443x over previous
#include <cuda_runtime.h>
#include <cuda_bf16.h>
#include <cstdint>

// ROI Align (torchvision semantics), OUT 7x7, adaptive grid <= 4x4.
// features: [B=4, C=256, H=200, W=272] fp32 NCHW
// rois:     [N=512, 5] (b, x1, y1, x2, y2) fp32
// out:      [N, C, 7, 7] fp32
//
// R8: R6's proven compute mapping (lane = channel -> broadcast LDS) restored,
// plus R7's orthogonal wins: dynamic staging extent (bulk-DMA only the rows/
// cols the ROI touches) and gw-templated unrolled tap loop.

#define OUT_H 7
#define OUT_W 7
#define NBINS 49
#define MAXG  4
#define C_TILE 8
#define REG   30               // max staged rows
#define WCOLS 36               // staged row pitch in floats (144B)
#define CPITCH 1084            // floats per channel: 30*36 +4 pad; %32==28,
                               // *4 %16==0 (bulk dst align)

#define FEAT_C 256
#define FEAT_H 200
#define FEAT_W 272
#define FEAT_HW (FEAT_H * FEAT_W)

__device__ __forceinline__ uint32_t smem_u32(const void* p) {
    uint32_t a;
    asm("{ .reg .u64 t; cvta.to.shared.u64 t, %1; cvt.u32.u64 %0, t; }"
        : "=r"(a) : "l"(p));
    return a;
}

struct __align__(16) SmemLayout {
    float    region[C_TILE * CPITCH];   // [c][row][36]
    float    s_out[C_TILE * NBINS];
    float4   ymeta[OUT_H * MAXG];       // wy0, wy1, rl*36, rh*36
    float4   xmeta[OUT_H * MAXG];       // wx0, wx1, cl, ch
    unsigned long long mbar;
};

// accumulate one bin for one channel (R6 mapping: 8 lanes share tap addrs)
template<int GW>
__device__ __forceinline__ float bin_acc(const float* __restrict__ regc,
                                         const float4* __restrict__ ym,
                                         const float4* __restrict__ xm,
                                         int gh)
{
    float acc = 0.0f;
    for (int iy = 0; iy < gh; ++iy) {
        const float4 my = ym[iy];
        const int ol = __float_as_int(my.z);
        const int oh = __float_as_int(my.w);
        #pragma unroll
        for (int ix = 0; ix < GW; ++ix) {
            const float4 mx = xm[ix];
            const int cl = __float_as_int(mx.z);
            const int ch = __float_as_int(mx.w);
            const float t0 = mx.x * regc[ol + cl] + mx.y * regc[ol + ch];
            const float t1 = mx.x * regc[oh + cl] + mx.y * regc[oh + ch];
            acc += my.x * t0 + my.y * t1;
        }
    }
    return acc;
}

template<int GW>
__device__ __forceinline__ void compute_bins(const SmemLayout& sm, float* s_out,
                                             int tid, int gh, float inv)
{
    const int c   = tid & (C_TILE - 1);
    const int grp = tid >> 3;             // 32 bin groups
    const float* regc = sm.region + c * CPITCH;
    #pragma unroll
    for (int bin = grp; bin < NBINS; bin += 32) {
        const int ph = bin / OUT_W;
        const int pw = bin - ph * OUT_W;
        const float4* ym = sm.ymeta + ph * MAXG;
        const float4* xm = sm.xmeta + pw * MAXG;
        s_out[c * NBINS + bin] = bin_acc<GW>(regc, ym, xm, gh) * inv;
    }
}

__global__ __launch_bounds__(256)
void roi_align_kernel(const float* __restrict__ feat,
                      const float* __restrict__ rois,
                      float* __restrict__ out)
{
    __shared__ SmemLayout sm;

    const int H = FEAT_H, W = FEAT_W;
    const int blk = blockIdx.x;
    const int n   = blk & 511;        // roi index
    const int ct  = blk >> 9;         // channel tile (slice-major for L2 reuse)

    const float* r = rois + n * 5;
    const int   bidx  = (int)r[0];
    const float x1    = r[1];
    const float y1    = r[2];
    const float roi_w = fmaxf(r[3] - x1, 1.0f);
    const float roi_h = fmaxf(r[4] - y1, 1.0f);
    const float bin_h = roi_h * (1.0f / OUT_H);
    const float bin_w = roi_w * (1.0f / OUT_W);
    int gh = (int)ceilf(roi_h * (1.0f / OUT_H)); gh = min(max(gh, 1), MAXG);
    int gw = (int)ceilf(roi_w * (1.0f / OUT_W)); gw = min(max(gw, 1), MAXG);

    const int ry0 = min(max((int)floorf(y1), 0), H - 1);
    const int rx0 = min(max((int)floorf(x1), 0), W - 1);
    const int ax0 = min(rx0 & ~3, W - WCOLS);   // aligned window, in-bounds

    // dynamic staged extent
    const int ymax = min((int)floorf(y1 + roi_h) + 1, H - 1);
    const int rows_used = min(REG, ymax - ry0 + 1);             // >= 1
    const int xmax = min((int)floorf(x1 + roi_w) + 1, W - 1);
    const int cols_f = min(WCOLS, ((xmax - ax0 + 1 + 3) & ~3)); // mult of 4
    const int cols_bytes = cols_f * 4;                          // mult of 16

    const int tid = threadIdx.x;
    const uint32_t mbar = smem_u32(&sm.mbar);

    // ---- init mbarrier + expect exact staging byte count ----
    if (tid == 0) {
        asm volatile("mbarrier.init.shared.b64 [%0], 1;" :: "r"(mbar) : "memory");
        asm volatile("mbarrier.arrive.expect_tx.shared.b64 _, [%0], %1;"
                     :: "r"(mbar), "r"(C_TILE * rows_used * cols_bytes) : "memory");
    }
    __syncthreads();

    // ---- phase 1: enqueue bulk row copies (only the rows we need) ----
    if (tid < C_TILE * REG) {
        const int c   = tid / REG;
        const int row = tid - c * REG;
        if (row < rows_used) {
            const float* src = feat
                + ((size_t)bidx * FEAT_C + (size_t)(ct * C_TILE + c)) * (size_t)FEAT_HW
                + (size_t)(ry0 + row) * W + ax0;
            const uint32_t dst = smem_u32(sm.region)
                               + (uint32_t)((c * CPITCH + row * WCOLS) * 4);
            asm volatile(
                "cp.async.bulk.shared::cluster.global.mbarrier::complete_tx::bytes "
                "[%0], [%1], %2, [%3];"
                :: "r"(dst), "l"(src), "r"(cols_bytes), "r"(mbar) : "memory");
        }
    }

    // ---- phase 0 (overlapped with DMA): weights + premult clamped offsets ----
    if (tid < 2 * OUT_H * MAXG) {
        const bool isx = (tid >= OUT_H * MAXG);
        const int  t   = isx ? tid - OUT_H * MAXG : tid;
        const int  p   = t >> 2;          // output bin index along axis
        const int  gg  = t & 3;           // grid slot
        const float start = isx ? x1 : y1;
        const float binsz = isx ? bin_w : bin_h;
        const int   gcnt  = isx ? gw : gh;
        const int   size  = isx ? W : H;
        const float pos = start + (float)p * binsz + ((float)gg + 0.5f) * binsz / (float)gcnt;
        const bool valid = (pos >= -1.0f) && (pos <= (float)size);
        float pp = fmaxf(pos, 0.0f);
        int low = min((int)floorf(pp), size - 1);
        if (low >= size - 1) pp = (float)(size - 1);
        const float frac = pp - (float)low;
        const float m = valid ? 1.0f : 0.0f;
        const int hi = min(low + 1, size - 1);
        float4 mv;
        mv.x = (1.0f - frac) * m;
        mv.y = frac * m;
        if (isx) {
            mv.z = __int_as_float(min(max(low - ax0, 0), cols_f - 1));
            mv.w = __int_as_float(min(max(hi  - ax0, 0), cols_f - 1));
            sm.xmeta[t] = mv;
        } else {
            mv.z = __int_as_float(min(max(low - ry0, 0), rows_used - 1) * WCOLS);
            mv.w = __int_as_float(min(max(hi  - ry0, 0), rows_used - 1) * WCOLS);
            sm.ymeta[t] = mv;
        }
    }

    // ---- wait for DMA completion (parity 0: fresh barrier each launch) ----
    asm volatile(
        "{\n\t"
        ".reg .pred P;\n\t"
        "WAIT_%=:\n\t"
        "mbarrier.try_wait.parity.acquire.cta.shared::cta.b64 P, [%0], 0, 0x989680;\n\t"
        "@P bra DONE_%=;\n\t"
        "bra WAIT_%=;\n\t"
        "DONE_%=:\n\t"
        "}"
        :: "r"(mbar) : "memory");
    __syncthreads();   // also covers meta visibility

    // ---- phase 2: R6 mapping (lane = channel), gw-specialized ----
    {
        const float inv = 1.0f / (float)(gh * gw);
        switch (gw) {
            case 1:  compute_bins<1>(sm, sm.s_out, tid, gh, inv); break;
            case 2:  compute_bins<2>(sm, sm.s_out, tid, gh, inv); break;
            case 3:  compute_bins<3>(sm, sm.s_out, tid, gh, inv); break;
            default: compute_bins<4>(sm, sm.s_out, tid, gh, inv); break;
        }
    }
    __syncthreads();

    // ---- phase 3: coalesced float4 output write ----
    {
        float4* ob4 = (float4*)(out + ((size_t)n * FEAT_C + (size_t)ct * C_TILE) * NBINS);
        const float4* so4 = (const float4*)sm.s_out;
        if (tid < (C_TILE * NBINS) / 4)      // 98 threads x 16B
            ob4[tid] = so4[tid];
    }
}

extern "C" void kernel_launch(void* const* d_in, const int* in_sizes, int n_in,
                              void* d_out, int out_size)
{
    const float* feat = (const float*)d_in[0];
    const float* rois = (const float*)d_in[1];
    float* out = (float*)d_out;
    const int N = in_sizes[1] / 5;

    roi_align_kernel<<<N * (FEAT_C / C_TILE), 256>>>(feat, rois, out);
}

// round 9
// speedup vs baseline: 1.3266x; 1.0661x over previous
#include <cuda_runtime.h>
#include <cuda_bf16.h>
#include <cstdint>

// ROI Align (torchvision semantics), OUT 7x7, adaptive grid <= 4x4.
// features: [B=4, C=256, H=200, W=272] fp32 NCHW
// rois:     [N=512, 5] (b, x1, y1, x2, y2) fp32
// out:      [N, C, 7, 7] fp32
//
// R9: instruction-cut pass on the R8 winner:
//  - x-meta preloaded into registers per bin (saves (gh-1)*gw LDS.128+decode)
//  - phase-1 enqueue index via shift/mask (no div-by-30)
//  - invariant pointer hoisting in the tap loop

#define OUT_H 7
#define OUT_W 7
#define NBINS 49
#define MAXG  4
#define C_TILE 8
#define REG   30               // max staged rows
#define WCOLS 36               // staged row pitch in floats (144B)
#define CPITCH 1084            // floats per channel: 30*36 +4 pad; %32==28,
                               // *4 %16==0 (bulk dst align)

#define FEAT_C 256
#define FEAT_H 200
#define FEAT_W 272
#define FEAT_HW (FEAT_H * FEAT_W)

__device__ __forceinline__ uint32_t smem_u32(const void* p) {
    uint32_t a;
    asm("{ .reg .u64 t; cvta.to.shared.u64 t, %1; cvt.u32.u64 %0, t; }"
        : "=r"(a) : "l"(p));
    return a;
}

struct __align__(16) SmemLayout {
    float    region[C_TILE * CPITCH];   // [c][row][36]
    float    s_out[C_TILE * NBINS];
    float4   ymeta[OUT_H * MAXG];       // wy0, wy1, rl*36, rh*36
    float4   xmeta[OUT_H * MAXG];       // wx0, wx1, cl, ch
    unsigned long long mbar;
};

// one bin, one channel. x-meta held in registers; 8 lanes share tap addrs.
template<int GW>
__device__ __forceinline__ float bin_acc(const float* __restrict__ regc,
                                         const float4* __restrict__ ym,
                                         const float4* __restrict__ xm,
                                         int gh)
{
    // preload & decode x meta once per bin
    float wx0[GW], wx1[GW];
    int   cl[GW],  ch[GW];
    #pragma unroll
    for (int ix = 0; ix < GW; ++ix) {
        const float4 mx = xm[ix];
        wx0[ix] = mx.x;  wx1[ix] = mx.y;
        cl[ix] = __float_as_int(mx.z);
        ch[ix] = __float_as_int(mx.w);
    }
    float acc = 0.0f;
    for (int iy = 0; iy < gh; ++iy) {
        const float4 my = ym[iy];
        const float* rlo = regc + __float_as_int(my.z);
        const float* rhi = regc + __float_as_int(my.w);
        float row_acc0 = 0.0f, row_acc1 = 0.0f;
        #pragma unroll
        for (int ix = 0; ix < GW; ++ix) {
            row_acc0 += wx0[ix] * rlo[cl[ix]] + wx1[ix] * rlo[ch[ix]];
            row_acc1 += wx0[ix] * rhi[cl[ix]] + wx1[ix] * rhi[ch[ix]];
        }
        acc += my.x * row_acc0 + my.y * row_acc1;
    }
    return acc;
}

template<int GW>
__device__ __forceinline__ void compute_bins(const SmemLayout& sm, float* s_out,
                                             int tid, int gh, float inv)
{
    const int c   = tid & (C_TILE - 1);
    const int grp = tid >> 3;             // 32 bin groups
    const float* regc = sm.region + c * CPITCH;
    #pragma unroll
    for (int bin = grp; bin < NBINS; bin += 32) {
        const int ph = bin / OUT_W;
        const int pw = bin - ph * OUT_W;
        const float4* ym = sm.ymeta + ph * MAXG;
        const float4* xm = sm.xmeta + pw * MAXG;
        s_out[c * NBINS + bin] = bin_acc<GW>(regc, ym, xm, gh) * inv;
    }
}

__global__ __launch_bounds__(256)
void roi_align_kernel(const float* __restrict__ feat,
                      const float* __restrict__ rois,
                      float* __restrict__ out)
{
    __shared__ SmemLayout sm;

    const int H = FEAT_H, W = FEAT_W;
    const int blk = blockIdx.x;
    const int n   = blk & 511;        // roi index
    const int ct  = blk >> 9;         // channel tile (slice-major for L2 reuse)

    const float* r = rois + n * 5;
    const int   bidx  = (int)r[0];
    const float x1    = r[1];
    const float y1    = r[2];
    const float roi_w = fmaxf(r[3] - x1, 1.0f);
    const float roi_h = fmaxf(r[4] - y1, 1.0f);
    const float bin_h = roi_h * (1.0f / OUT_H);
    const float bin_w = roi_w * (1.0f / OUT_W);
    int gh = (int)ceilf(roi_h * (1.0f / OUT_H)); gh = min(max(gh, 1), MAXG);
    int gw = (int)ceilf(roi_w * (1.0f / OUT_W)); gw = min(max(gw, 1), MAXG);

    const int ry0 = min(max((int)floorf(y1), 0), H - 1);
    const int rx0 = min(max((int)floorf(x1), 0), W - 1);
    const int ax0 = min(rx0 & ~3, W - WCOLS);   // aligned window, in-bounds

    // dynamic staged extent
    const int ymax = min((int)floorf(y1 + roi_h) + 1, H - 1);
    const int rows_used = min(REG, ymax - ry0 + 1);             // >= 1
    const int xmax = min((int)floorf(x1 + roi_w) + 1, W - 1);
    const int cols_f = min(WCOLS, ((xmax - ax0 + 1 + 3) & ~3)); // mult of 4
    const int cols_bytes = cols_f * 4;                          // mult of 16

    const int tid = threadIdx.x;
    const uint32_t mbar = smem_u32(&sm.mbar);

    // ---- init mbarrier + expect exact staging byte count ----
    if (tid == 0) {
        asm volatile("mbarrier.init.shared.b64 [%0], 1;" :: "r"(mbar) : "memory");
        asm volatile("mbarrier.arrive.expect_tx.shared.b64 _, [%0], %1;"
                     :: "r"(mbar), "r"(C_TILE * rows_used * cols_bytes) : "memory");
    }
    __syncthreads();

    // ---- phase 1: enqueue bulk row copies (shift/mask mapping) ----
    {
        const int c   = tid >> 5;         // 0..7
        const int row = tid & 31;         // 0..31; rows >= rows_used skipped
        if (row < rows_used) {
            const float* src = feat
                + ((size_t)bidx * FEAT_C + (size_t)(ct * C_TILE + c)) * (size_t)FEAT_HW
                + (size_t)(ry0 + row) * W + ax0;
            const uint32_t dst = smem_u32(sm.region)
                               + (uint32_t)((c * CPITCH + row * WCOLS) * 4);
            asm volatile(
                "cp.async.bulk.shared::cluster.global.mbarrier::complete_tx::bytes "
                "[%0], [%1], %2, [%3];"
                :: "r"(dst), "l"(src), "r"(cols_bytes), "r"(mbar) : "memory");
        }
    }

    // ---- phase 0 (overlapped with DMA): weights + premult clamped offsets ----
    if (tid < 2 * OUT_H * MAXG) {
        const bool isx = (tid >= OUT_H * MAXG);
        const int  t   = isx ? tid - OUT_H * MAXG : tid;
        const int  p   = t >> 2;          // output bin index along axis
        const int  gg  = t & 3;           // grid slot
        const float start = isx ? x1 : y1;
        const float binsz = isx ? bin_w : bin_h;
        const int   gcnt  = isx ? gw : gh;
        const int   size  = isx ? W : H;
        const float pos = start + (float)p * binsz + ((float)gg + 0.5f) * binsz / (float)gcnt;
        const bool valid = (pos >= -1.0f) && (pos <= (float)size);
        float pp = fmaxf(pos, 0.0f);
        int low = min((int)floorf(pp), size - 1);
        if (low >= size - 1) pp = (float)(size - 1);
        const float frac = pp - (float)low;
        const float m = valid ? 1.0f : 0.0f;
        const int hi = min(low + 1, size - 1);
        float4 mv;
        mv.x = (1.0f - frac) * m;
        mv.y = frac * m;
        if (isx) {
            mv.z = __int_as_float(min(max(low - ax0, 0), cols_f - 1));
            mv.w = __int_as_float(min(max(hi  - ax0, 0), cols_f - 1));
            sm.xmeta[t] = mv;
        } else {
            mv.z = __int_as_float(min(max(low - ry0, 0), rows_used - 1) * WCOLS);
            mv.w = __int_as_float(min(max(hi  - ry0, 0), rows_used - 1) * WCOLS);
            sm.ymeta[t] = mv;
        }
    }

    // ---- wait for DMA completion (parity 0: fresh barrier each launch) ----
    asm volatile(
        "{\n\t"
        ".reg .pred P;\n\t"
        "WAIT_%=:\n\t"
        "mbarrier.try_wait.parity.acquire.cta.shared::cta.b64 P, [%0], 0, 0x989680;\n\t"
        "@P bra DONE_%=;\n\t"
        "bra WAIT_%=;\n\t"
        "DONE_%=:\n\t"
        "}"
        :: "r"(mbar) : "memory");
    __syncthreads();   // also covers meta visibility

    // ---- phase 2: lane = channel mapping, gw-specialized ----
    {
        const float inv = 1.0f / (float)(gh * gw);
        switch (gw) {
            case 1:  compute_bins<1>(sm, sm.s_out, tid, gh, inv); break;
            case 2:  compute_bins<2>(sm, sm.s_out, tid, gh, inv); break;
            case 3:  compute_bins<3>(sm, sm.s_out, tid, gh, inv); break;
            default: compute_bins<4>(sm, sm.s_out, tid, gh, inv); break;
        }
    }
    __syncthreads();

    // ---- phase 3: coalesced float4 output write ----
    {
        float4* ob4 = (float4*)(out + ((size_t)n * FEAT_C + (size_t)ct * C_TILE) * NBINS);
        const float4* so4 = (const float4*)sm.s_out;
        if (tid < (C_TILE * NBINS) / 4)      // 98 threads x 16B
            ob4[tid] = so4[tid];
    }
}

extern "C" void kernel_launch(void* const* d_in, const int* in_sizes, int n_in,
                              void* d_out, int out_size)
{
    const float* feat = (const float*)d_in[0];
    const float* rois = (const float*)d_in[1];
    float* out = (float*)d_out;
    const int N = in_sizes[1] / 5;

    roi_align_kernel<<<N * (FEAT_C / C_TILE), 256>>>(feat, rois, out);
}